// round 1
// baseline (speedup 1.0000x reference)
#include <cuda_runtime.h>
#include <cstdint>

// Problem constants (fixed shapes from reference)
#define N_ROWS   262144         // 64*64*64
#define DIMS     64
#define KCODES   1024
#define BM       128            // rows per block
#define BK       128            // codes per tile
#define NTILES   (KCODES / BK)  // 8
#define THREADS  256
#define AS_LD    132            // padded leading dim for As [k][m]
#define QOUT     (N_ROWS * DIMS)  // 16777216 floats of quantized_st
#define SMEM_FLOATS (DIMS * AS_LD + 2 * DIMS * BK)  // 8448 + 16384 = 24832
#define SMEM_BYTES  (SMEM_FLOATS * 4)               // 99328

// Scratch (no allocation allowed -> device globals)
__device__ __align__(16) float        g_cnorm[KCODES];
__device__ unsigned int               g_counts[KCODES];
__device__ float                      g_loss[2];   // [0]=sum_e, [1]=sum_q

// ---------------- f32x2 helpers (packed fp32 FMA, sm_100+) ----------------
static __device__ __forceinline__ unsigned long long dup2(float v) {
    unsigned long long r;
    asm("mov.b64 %0, {%1, %1};" : "=l"(r) : "f"(v));
    return r;
}
static __device__ __forceinline__ void up2(unsigned long long v, float& lo, float& hi) {
    asm("mov.b64 {%0, %1}, %2;" : "=f"(lo), "=f"(hi) : "l"(v));
}
static __device__ __forceinline__ unsigned long long ffma2(
    unsigned long long a, unsigned long long b, unsigned long long c) {
    unsigned long long d;
    asm("fma.rn.f32x2 %0, %1, %2, %3;" : "=l"(d) : "l"(a), "l"(b), "l"(c));
    return d;
}

// ---------------- init: zero counts + loss accumulators ----------------
__global__ void vq_init() {
    int t = threadIdx.x;
    g_counts[t] = 0u;
    if (t < 2) g_loss[t] = 0.0f;
}

// ---------------- cnorm: 0.5*||c_k||^2 ----------------
__global__ void vq_cnorm(const float* __restrict__ cb) {
    int k = threadIdx.x;   // 1024 threads, 1 block
    const float4* c4 = (const float4*)(cb + k * DIMS);
    float s = 0.0f;
#pragma unroll
    for (int i = 0; i < DIMS / 4; i++) {
        float4 v = c4[i];
        s += v.x * v.x + v.y * v.y + v.z * v.z + v.w * v.w;
    }
    g_cnorm[k] = 0.5f * s;
}

// ---------------- main: fused distance-GEMM + argmax + gather + losses ----------------
extern __shared__ float smem[];

__global__ __launch_bounds__(THREADS, 1)
void vq_main(const float* __restrict__ inp, const float* __restrict__ cb,
             float* __restrict__ out)
{
    float* As = smem;                       // [k][m], 64 x 132 (padded)
    float* Bs = smem + DIMS * AS_LD;        // 2 x [k][c], 64 x 128 each

    const int tid  = threadIdx.x;
    const int rg   = tid >> 5;              // warp id: rows rg*16 .. rg*16+15
    const int lane = tid & 31;              // codes lane*4 .. lane*4+3 per tile
    const int row0 = blockIdx.x * BM;

    // ---- fill As (transpose inputs [m][k] -> [k][m]) : coalesced LDG ----
#pragma unroll
    for (int i = 0; i < 8; i++) {
        int chunk = tid + i * THREADS;      // 0..2047
        int m = chunk >> 4;
        int kq = chunk & 15;
        float4 v = *(const float4*)(inp + (size_t)(row0 + m) * DIMS + kq * 4);
        As[(kq * 4 + 0) * AS_LD + m] = v.x;
        As[(kq * 4 + 1) * AS_LD + m] = v.y;
        As[(kq * 4 + 2) * AS_LD + m] = v.z;
        As[(kq * 4 + 3) * AS_LD + m] = v.w;
    }
    // ---- fill Bs tile 0 (transpose codebook [c][k] -> [k][c]) : conflict-free STS ----
#pragma unroll
    for (int i = 0; i < 8; i++) {
        int c  = (tid & 31) | ((i & 3) << 5);
        int kq = ((tid >> 5) << 1) | (i >> 2);
        float4 v = *(const float4*)(cb + c * DIMS + kq * 4);
        Bs[(kq * 4 + 0) * BK + c] = v.x;
        Bs[(kq * 4 + 1) * BK + c] = v.y;
        Bs[(kq * 4 + 2) * BK + c] = v.z;
        Bs[(kq * 4 + 3) * BK + c] = v.w;
    }
    __syncthreads();

    float best[16];
    int   bidx[16];
#pragma unroll
    for (int r = 0; r < 16; r++) { best[r] = -3.4e38f; bidx[r] = 0; }

    const float* Abase = As + rg * 16;

    for (int t = 0; t < NTILES; ++t) {
        // prefetch next codebook tile into registers (overlap with compute)
        float4 pf[8];
        if (t + 1 < NTILES) {
#pragma unroll
            for (int i = 0; i < 8; i++) {
                int c  = (tid & 31) | ((i & 3) << 5);
                int kq = ((tid >> 5) << 1) | (i >> 2);
                pf[i] = *(const float4*)(cb + (size_t)(t + 1) * BK * DIMS + c * DIMS + kq * 4);
            }
        }

        const float* B = Bs + (t & 1) * (DIMS * BK);

        // init accumulators to -0.5*||c||^2 so acc == score
        float4 hn = *(const float4*)(g_cnorm + t * BK + lane * 4);
        unsigned long long acc[8][4];
        {
            unsigned long long i0 = dup2(-hn.x), i1 = dup2(-hn.y),
                               i2 = dup2(-hn.z), i3 = dup2(-hn.w);
#pragma unroll
            for (int p = 0; p < 8; p++) {
                acc[p][0] = i0; acc[p][1] = i1; acc[p][2] = i2; acc[p][3] = i3;
            }
        }

        // ---- k loop: 16 rows x 4 codes via 32 f32x2 FMAs per k ----
#pragma unroll 8
        for (int k = 0; k < DIMS; k++) {
            const ulonglong2* ap = (const ulonglong2*)(Abase + k * AS_LD);
            ulonglong2 a01 = ap[0];
            ulonglong2 a23 = ap[1];
            ulonglong2 a45 = ap[2];
            ulonglong2 a67 = ap[3];
            float4 bv = *(const float4*)(B + k * BK + lane * 4);
            unsigned long long b0 = dup2(bv.x), b1 = dup2(bv.y),
                               b2 = dup2(bv.z), b3 = dup2(bv.w);
            unsigned long long a[8] = { a01.x, a01.y, a23.x, a23.y,
                                        a45.x, a45.y, a67.x, a67.y };
#pragma unroll
            for (int p = 0; p < 8; p++) {
                acc[p][0] = ffma2(a[p], b0, acc[p][0]);
                acc[p][1] = ffma2(a[p], b1, acc[p][1]);
                acc[p][2] = ffma2(a[p], b2, acc[p][2]);
                acc[p][3] = ffma2(a[p], b3, acc[p][3]);
            }
        }

        // ---- fold tile scores into running per-row best (codes ascending) ----
        int cbase = t * BK + lane * 4;
#pragma unroll
        for (int p = 0; p < 8; p++) {
#pragma unroll
            for (int j = 0; j < 4; j++) {
                float s0, s1;
                up2(acc[p][j], s0, s1);
                if (s0 > best[2 * p])     { best[2 * p]     = s0; bidx[2 * p]     = cbase + j; }
                if (s1 > best[2 * p + 1]) { best[2 * p + 1] = s1; bidx[2 * p + 1] = cbase + j; }
            }
        }

        // ---- stage next tile into the other smem buffer ----
        if (t + 1 < NTILES) {
            __syncthreads();
            float* Bn = Bs + ((t + 1) & 1) * (DIMS * BK);
#pragma unroll
            for (int i = 0; i < 8; i++) {
                int c  = (tid & 31) | ((i & 3) << 5);
                int kq = ((tid >> 5) << 1) | (i >> 2);
                Bn[(kq * 4 + 0) * BK + c] = pf[i].x;
                Bn[(kq * 4 + 1) * BK + c] = pf[i].y;
                Bn[(kq * 4 + 2) * BK + c] = pf[i].z;
                Bn[(kq * 4 + 3) * BK + c] = pf[i].w;
            }
            __syncthreads();
        }
    }

    // ---- warp-wide argmax per row (all 32 lanes share the same 16 rows) ----
#pragma unroll
    for (int r = 0; r < 16; r++) {
        float s = best[r];
        int   ix = bidx[r];
#pragma unroll
        for (int off = 16; off > 0; off >>= 1) {
            float os = __shfl_xor_sync(0xffffffffu, s, off);
            int   oi = __shfl_xor_sync(0xffffffffu, ix, off);
            if (os > s || (os == s && oi < ix)) { s = os; ix = oi; }
        }
        best[r] = s;
        bidx[r] = ix;
    }

    // ---- epilogue: gather quantized, straight-through, losses, tokens, counts ----
    float esum = 0.0f, qsum = 0.0f;
    const int mbase = rg * 16;
    for (int r = 0; r < 16; r++) {
        int ix = bidx[r];
        int m = mbase + r;
        int grow = row0 + m;
        float2 c2 = *(const float2*)(cb + ix * DIMS + lane * 2);
        float x0 = As[(lane * 2)     * AS_LD + m];
        float x1 = As[(lane * 2 + 1) * AS_LD + m];
        float d0 = c2.x - x0;
        float d1 = c2.y - x1;
        float q0 = x0 + d0;           // straight-through value (matches jnp rounding chain)
        float q1 = x1 + d1;
        float e0 = q0 - x0;
        float e1 = q1 - x1;
        esum += e0 * e0 + e1 * e1;
        qsum += d0 * d0 + d1 * d1;
        *(float2*)(out + (size_t)grow * DIMS + lane * 2) = make_float2(q0, q1);
        if (lane == 0) {
            atomicAdd(&g_counts[ix], 1u);
            out[QOUT + grow] = (float)ix;     // tokens (as output-dtype float)
        }
    }
#pragma unroll
    for (int off = 16; off > 0; off >>= 1) {
        esum += __shfl_xor_sync(0xffffffffu, esum, off);
        qsum += __shfl_xor_sync(0xffffffffu, qsum, off);
    }
    if (lane == 0) {
        atomicAdd(&g_loss[0], esum);
        atomicAdd(&g_loss[1], qsum);
    }
}

// ---------------- finalize: perplexity + scalar losses ----------------
__global__ void vq_finalize(float* __restrict__ out) {
    __shared__ float red[1024];
    int t = threadIdx.x;
    float p = (float)g_counts[t] / (float)N_ROWS;
    red[t] = -p * logf(p + 1e-10f);
    __syncthreads();
    for (int s = 512; s > 0; s >>= 1) {
        if (t < s) red[t] += red[t + s];
        __syncthreads();
    }
    if (t == 0) {
        float inv = 1.0f / (float)((long long)N_ROWS * DIMS);
        float e_mean = g_loss[0] * inv;
        float q_mean = g_loss[1] * inv;
        float commit = 0.25f * e_mean;
        float H = red[0];
        out[QOUT + N_ROWS + 0] = commit + q_mean;   // vq_loss
        out[QOUT + N_ROWS + 1] = commit;            // commitment_loss
        out[QOUT + N_ROWS + 2] = q_mean;            // codebook_loss
        out[QOUT + N_ROWS + 3] = expf(H);           // perplexity
    }
}

extern "C" void kernel_launch(void* const* d_in, const int* in_sizes, int n_in,
                              void* d_out, int out_size)
{
    const float* inp = (const float*)d_in[0];
    const float* cb  = (const float*)d_in[1];
    float* out = (float*)d_out;

    cudaFuncSetAttribute(vq_main, cudaFuncAttributeMaxDynamicSharedMemorySize, SMEM_BYTES);

    vq_init<<<1, 1024>>>();
    vq_cnorm<<<1, 1024>>>(cb);
    vq_main<<<N_ROWS / BM, THREADS, SMEM_BYTES>>>(inp, cb, out);
    vq_finalize<<<1, 1024>>>(out);
}

// round 5
// speedup vs baseline: 1.0999x; 1.0999x over previous
#include <cuda_runtime.h>
#include <cuda_bf16.h>
#include <cstdint>

// ---------------- problem constants ----------------
#define N_ROWS   262144
#define DIMS     64
#define KCODES   1024
#define BM       128
#define THREADS  512
#define QOUT     (N_ROWS * DIMS)
#define CAND_CAP 8

// ---------------- smem layout (bytes) ----------------
#define SM_X     0                          // 128 x 272B fp32 rows (padded)
#define SM_A     34816                      // 128 x 144B bf16 rows (padded)
#define SM_B     53248                      // 1024 x 144B bf16 rows (padded)
#define SM_CN    200704                     // 1024 fp32
#define SM_RMAX  204800                     // 128 u32 keys
#define SM_CNT   205312                     // 128 int
#define SM_CAND  205824                     // 128 x 8 x 8B
#define SM_TOK   214016                     // 128 int
#define SM_DELTA 214528                     // 128 fp32
#define SMEM_TOTAL 215040

#define A_STRIDE 144
#define B_STRIDE 144
#define X_STRIDE 272

// ---------------- device globals ----------------
__device__ __align__(16) float    g_cnorm[KCODES];
__device__ __align__(16) uint32_t g_cbbf16[KCODES * DIMS / 2];
__device__ unsigned int           g_counts[KCODES];
__device__ float                  g_loss[2];
__device__ int                    g_cmax_bits;

// ---------------- helpers ----------------
static __device__ __forceinline__ unsigned fkey(float f) {
    int b = __float_as_int(f);
    return (unsigned)(b >= 0 ? (b | 0x80000000) : ~b);
}
static __device__ __forceinline__ float finv(unsigned k) {
    int b = (k & 0x80000000u) ? (int)(k & 0x7fffffffu) : ~(int)k;
    return __int_as_float(b);
}
static __device__ __forceinline__ void mma16816(
    float& c0, float& c1, float& c2, float& c3,
    uint32_t a0, uint32_t a1, uint32_t a2, uint32_t a3,
    uint32_t b0, uint32_t b1)
{
    asm volatile(
        "mma.sync.aligned.m16n8k16.row.col.f32.bf16.bf16.f32 "
        "{%0,%1,%2,%3}, {%4,%5,%6,%7}, {%8,%9}, {%0,%1,%2,%3};"
        : "+f"(c0), "+f"(c1), "+f"(c2), "+f"(c3)
        : "r"(a0), "r"(a1), "r"(a2), "r"(a3), "r"(b0), "r"(b1));
}

// ---------------- init ----------------
__global__ void vq_init() {
    int t = threadIdx.x;
    g_counts[t] = 0u;
    if (t < 2) g_loss[t] = 0.0f;
    if (t == 2) g_cmax_bits = 0;
}

// ---------------- prep: cnorm, cmax, bf16 codebook ----------------
__global__ void vq_prep(const float* __restrict__ cb) {
    int k = threadIdx.x;   // 1024 threads, 1 block
    const float4* c4 = (const float4*)(cb + (size_t)k * DIMS);
    uint32_t* ob = g_cbbf16 + k * (DIMS / 2);
    float s = 0.0f;
#pragma unroll
    for (int j = 0; j < 16; j++) {
        float4 v = c4[j];
        s += v.x * v.x + v.y * v.y + v.z * v.z + v.w * v.w;
        __nv_bfloat162 p0 = __float22bfloat162_rn(make_float2(v.x, v.y));
        __nv_bfloat162 p1 = __float22bfloat162_rn(make_float2(v.z, v.w));
        ob[j * 2 + 0] = *(uint32_t*)&p0;
        ob[j * 2 + 1] = *(uint32_t*)&p1;
    }
    g_cnorm[k] = 0.5f * s;
    atomicMax(&g_cmax_bits, __float_as_int(sqrtf(s)));
}

// ---------------- main ----------------
extern __shared__ char smem[];

__global__ __launch_bounds__(THREADS, 1)
void vq_main(const float* __restrict__ inp, const float* __restrict__ cb,
             float* __restrict__ out)
{
    const int tid  = threadIdx.x;
    const int w    = tid >> 5;
    const int lane = tid & 31;
    const int row0 = blockIdx.x * BM;

    float*    Xs = (float*)(smem + SM_X);
    char*     As = smem + SM_A;
    char*     Bs = smem + SM_B;
    float*    CN = (float*)(smem + SM_CN);
    unsigned* RM = (unsigned*)(smem + SM_RMAX);
    int*      CT = (int*)(smem + SM_CNT);
    float2*   CA = (float2*)(smem + SM_CAND);
    int*      TK = (int*)(smem + SM_TOK);
    float*    DL = (float*)(smem + SM_DELTA);

    // ---- fills ----
    if (tid < 128) { RM[tid] = 0u; CT[tid] = 0; }
#pragma unroll
    for (int i = 0; i < 4; i++) {           // X fp32 + A bf16
        int idx = tid + i * THREADS;
        int r = idx >> 4, j = idx & 15;
        float4 v = *(const float4*)(inp + (size_t)(row0 + r) * DIMS + j * 4);
        *(float4*)(Xs + r * (X_STRIDE / 4) + j * 4) = v;
        __nv_bfloat162 p0 = __float22bfloat162_rn(make_float2(v.x, v.y));
        __nv_bfloat162 p1 = __float22bfloat162_rn(make_float2(v.z, v.w));
        *(uint2*)(As + r * A_STRIDE + j * 8) = make_uint2(*(uint32_t*)&p0, *(uint32_t*)&p1);
    }
#pragma unroll
    for (int i = 0; i < 16; i++) {          // B bf16
        int idx = tid + i * THREADS;
        int c = idx >> 3, j = idx & 7;
        uint4 v = *(const uint4*)(g_cbbf16 + (size_t)idx * 4);
        *(uint4*)(Bs + c * B_STRIDE + j * 16) = v;
    }
#pragma unroll
    for (int i = 0; i < 2; i++) {           // cnorm
        int idx = tid + i * THREADS;
        CN[idx] = g_cnorm[idx];
    }
    __syncthreads();

    // ---- per-row certified margin delta ----
    if (tid < 128) {
        const float4* xr = (const float4*)(Xs + tid * (X_STRIDE / 4));
        float s = 0.0f;
#pragma unroll
        for (int j = 0; j < 16; j++) {
            float4 v = xr[j];
            s += v.x * v.x + v.y * v.y + v.z * v.z + v.w * v.w;
        }
        DL[tid] = sqrtf(s) * __int_as_float(g_cmax_bits) * (2.2f / 256.0f) + 1e-4f;
    }
    __syncthreads();

    // ---- warp work assignment ----
    const int wrow  = (w & 7) * 16;         // 16 rows
    const int chalf = (w >> 3) * 512;       // 512 codes
    const int r0 = wrow + (lane >> 2);
    const int r1 = r0 + 8;

    // ---- A fragments: persistent registers ----
    uint32_t af[4][4];
#pragma unroll
    for (int ks = 0; ks < 4; ks++) {
        int kb = ks * 32 + (lane & 3) * 4;
        af[ks][0] = *(const uint32_t*)(As + r0 * A_STRIDE + kb);
        af[ks][1] = *(const uint32_t*)(As + r1 * A_STRIDE + kb);
        af[ks][2] = *(const uint32_t*)(As + r0 * A_STRIDE + kb + 16);
        af[ks][3] = *(const uint32_t*)(As + r1 * A_STRIDE + kb + 16);
    }

    // ================= PASS 1: exact approx-max per row =================
    float gm0[8], gm1[8];
#pragma unroll
    for (int g = 0; g < 8; g++) { gm0[g] = -3.4e38f; gm1[g] = -3.4e38f; }

    for (int j = 0; j < 64; j += 2) {
        float ac[2][4];
#pragma unroll
        for (int u = 0; u < 2; u++) {
            int col0 = chalf + (j + u) * 8 + (lane & 3) * 2;
            float2 cn = *(const float2*)(CN + col0);
            ac[u][0] = -cn.x; ac[u][1] = -cn.y;
            ac[u][2] = -cn.x; ac[u][3] = -cn.y;
        }
#pragma unroll
        for (int ks = 0; ks < 4; ks++) {
#pragma unroll
            for (int u = 0; u < 2; u++) {
                int bcol = chalf + (j + u) * 8 + (lane >> 2);
                const char* bp = Bs + bcol * B_STRIDE + ks * 32 + (lane & 3) * 4;
                uint32_t b0 = *(const uint32_t*)bp;
                uint32_t b1 = *(const uint32_t*)(bp + 16);
                mma16816(ac[u][0], ac[u][1], ac[u][2], ac[u][3],
                         af[ks][0], af[ks][1], af[ks][2], af[ks][3], b0, b1);
            }
        }
        int g = j >> 3;
#pragma unroll
        for (int u = 0; u < 2; u++) {
            gm0[g] = fmaxf(gm0[g], fmaxf(ac[u][0], ac[u][1]));
            gm1[g] = fmaxf(gm1[g], fmaxf(ac[u][2], ac[u][3]));
        }
    }
    // combine group maxes across the 4 lanes of each quad (rows identical there)
    float rm0 = -3.4e38f, rm1 = -3.4e38f;
#pragma unroll
    for (int g = 0; g < 8; g++) {
        gm0[g] = fmaxf(gm0[g], __shfl_xor_sync(0xffffffffu, gm0[g], 1));
        gm0[g] = fmaxf(gm0[g], __shfl_xor_sync(0xffffffffu, gm0[g], 2));
        gm1[g] = fmaxf(gm1[g], __shfl_xor_sync(0xffffffffu, gm1[g], 1));
        gm1[g] = fmaxf(gm1[g], __shfl_xor_sync(0xffffffffu, gm1[g], 2));
        rm0 = fmaxf(rm0, gm0[g]);
        rm1 = fmaxf(rm1, gm1[g]);
    }
    if ((lane & 3) == 0) {
        atomicMax(&RM[r0], fkey(rm0));
        atomicMax(&RM[r1], fkey(rm1));
    }
    __syncthreads();

    // ================= PASS 2: fixed-threshold candidate collection =================
    const float thr0 = finv(RM[r0]) - DL[r0];
    const float thr1 = finv(RM[r1]) - DL[r1];

    for (int j = 0; j < 64; j += 2) {
        int g = j >> 3;
        bool need = (gm0[g] >= thr0) || (gm1[g] >= thr1);
        if (!__any_sync(0xffffffffu, need)) continue;

        float ac[2][4];
        int   col0[2];
#pragma unroll
        for (int u = 0; u < 2; u++) {
            col0[u] = chalf + (j + u) * 8 + (lane & 3) * 2;
            float2 cn = *(const float2*)(CN + col0[u]);
            ac[u][0] = -cn.x; ac[u][1] = -cn.y;
            ac[u][2] = -cn.x; ac[u][3] = -cn.y;
        }
#pragma unroll
        for (int ks = 0; ks < 4; ks++) {
#pragma unroll
            for (int u = 0; u < 2; u++) {
                int bcol = chalf + (j + u) * 8 + (lane >> 2);
                const char* bp = Bs + bcol * B_STRIDE + ks * 32 + (lane & 3) * 4;
                uint32_t b0 = *(const uint32_t*)bp;
                uint32_t b1 = *(const uint32_t*)(bp + 16);
                mma16816(ac[u][0], ac[u][1], ac[u][2], ac[u][3],
                         af[ks][0], af[ks][1], af[ks][2], af[ks][3], b0, b1);
            }
        }
#pragma unroll
        for (int u = 0; u < 2; u++) {
#pragma unroll
            for (int e = 0; e < 2; e++) {
                if (ac[u][e] >= thr0) {
                    int p = atomicAdd(&CT[r0], 1);
                    if (p < CAND_CAP)
                        CA[r0 * CAND_CAP + p] =
                            make_float2(ac[u][e], __int_as_float(col0[u] + e));
                }
                if (ac[u][2 + e] >= thr1) {
                    int p = atomicAdd(&CT[r1], 1);
                    if (p < CAND_CAP)
                        CA[r1 * CAND_CAP + p] =
                            make_float2(ac[u][2 + e], __int_as_float(col0[u] + e));
                }
            }
        }
    }
    __syncthreads();

    // ---- exact fp32 rescore (1 thread per row) ----
    if (tid < 128) {
        int r = tid;
        int n = CT[r];
        const float* xrow = Xs + r * (X_STRIDE / 4);
        float bestS = -3.4e38f;
        int   bestI = KCODES;
        if (n <= CAND_CAP) {
            for (int i = 0; i < n; i++) {
                float2 ce = CA[r * CAND_CAP + i];
                int ix = __float_as_int(ce.y);
                const float4* c4 = (const float4*)(cb + (size_t)ix * DIMS);
                float a0 = 0.f, a1 = 0.f, a2 = 0.f, a3 = 0.f;
#pragma unroll
                for (int q = 0; q < 16; q++) {
                    float4 cv = c4[q];
                    float4 xv = *(const float4*)(xrow + q * 4);
                    a0 = fmaf(xv.x, cv.x, a0);
                    a1 = fmaf(xv.y, cv.y, a1);
                    a2 = fmaf(xv.z, cv.z, a2);
                    a3 = fmaf(xv.w, cv.w, a3);
                }
                float s = (a0 + a1) + (a2 + a3) - CN[ix];
                if (s > bestS || (s == bestS && ix < bestI)) { bestS = s; bestI = ix; }
            }
        } else {
            // overflow fallback (probability ~1e-7/row): exact full scan
            for (int ix = 0; ix < KCODES; ix++) {
                const float4* c4 = (const float4*)(cb + (size_t)ix * DIMS);
                float a0 = 0.f, a1 = 0.f, a2 = 0.f, a3 = 0.f;
#pragma unroll
                for (int q = 0; q < 16; q++) {
                    float4 cv = c4[q];
                    float4 xv = *(const float4*)(xrow + q * 4);
                    a0 = fmaf(xv.x, cv.x, a0);
                    a1 = fmaf(xv.y, cv.y, a1);
                    a2 = fmaf(xv.z, cv.z, a2);
                    a3 = fmaf(xv.w, cv.w, a3);
                }
                float s = (a0 + a1) + (a2 + a3) - CN[ix];
                if (s > bestS) { bestS = s; bestI = ix; }
            }
        }
        TK[r] = bestI;
        out[QOUT + row0 + r] = (float)bestI;
        atomicAdd(&g_counts[bestI], 1u);
    }
    __syncthreads();

    // ---- quantized + straight-through + losses (cooperative, coalesced) ----
    float esum = 0.0f, qsum = 0.0f;
#pragma unroll
    for (int i = 0; i < 4; i++) {
        int idx = tid + i * THREADS;
        int r = idx >> 4, q = idx & 15;
        int ix = TK[r];
        float4 cv = *(const float4*)(cb + (size_t)ix * DIMS + q * 4);
        float4 xv = *(const float4*)(Xs + r * (X_STRIDE / 4) + q * 4);
        float d0v = cv.x - xv.x, d1v = cv.y - xv.y, d2v = cv.z - xv.z, d3v = cv.w - xv.w;
        float q0 = xv.x + d0v, q1 = xv.y + d1v, q2 = xv.z + d2v, q3 = xv.w + d3v;
        float e0 = q0 - xv.x, e1 = q1 - xv.y, e2 = q2 - xv.z, e3 = q3 - xv.w;
        esum += e0 * e0 + e1 * e1 + e2 * e2 + e3 * e3;
        qsum += d0v * d0v + d1v * d1v + d2v * d2v + d3v * d3v;
        *(float4*)(out + (size_t)(row0 + r) * DIMS + q * 4) = make_float4(q0, q1, q2, q3);
    }
#pragma unroll
    for (int off = 16; off > 0; off >>= 1) {
        esum += __shfl_xor_sync(0xffffffffu, esum, off);
        qsum += __shfl_xor_sync(0xffffffffu, qsum, off);
    }
    if (lane == 0) {
        atomicAdd(&g_loss[0], esum);
        atomicAdd(&g_loss[1], qsum);
    }
}

// ---------------- finalize ----------------
__global__ void vq_finalize(float* __restrict__ out) {
    __shared__ float red[1024];
    int t = threadIdx.x;
    float p = (float)g_counts[t] / (float)N_ROWS;
    red[t] = -p * logf(p + 1e-10f);
    __syncthreads();
    for (int s = 512; s > 0; s >>= 1) {
        if (t < s) red[t] += red[t + s];
        __syncthreads();
    }
    if (t == 0) {
        float inv = 1.0f / (float)((long long)N_ROWS * DIMS);
        float e_mean = g_loss[0] * inv;
        float q_mean = g_loss[1] * inv;
        float commit = 0.25f * e_mean;
        out[QOUT + N_ROWS + 0] = commit + q_mean;
        out[QOUT + N_ROWS + 1] = commit;
        out[QOUT + N_ROWS + 2] = q_mean;
        out[QOUT + N_ROWS + 3] = expf(red[0]);
    }
}

extern "C" void kernel_launch(void* const* d_in, const int* in_sizes, int n_in,
                              void* d_out, int out_size)
{
    const float* inp = (const float*)d_in[0];
    const float* cb  = (const float*)d_in[1];
    float* out = (float*)d_out;

    cudaFuncSetAttribute(vq_main, cudaFuncAttributeMaxDynamicSharedMemorySize, SMEM_TOTAL);

    vq_init<<<1, 1024>>>();
    vq_prep<<<1, 1024>>>(cb);
    vq_main<<<N_ROWS / BM, THREADS, SMEM_TOTAL>>>(inp, cb, out);
    vq_finalize<<<1, 1024>>>(out);
}

// round 6
// speedup vs baseline: 1.2161x; 1.1057x over previous
#include <cuda_runtime.h>
#include <cuda_bf16.h>
#include <cstdint>

// ---------------- problem constants ----------------
#define N_ROWS   262144
#define DIMS     64
#define KCODES   1024
#define BM       128
#define THREADS  512
#define GRID     (N_ROWS / BM)              // 2048
#define QOUT     (N_ROWS * DIMS)
#define CAND_CAP 8

// ---------------- smem layout (bytes) ----------------
#define SM_X     0                          // 128 x 272B fp32 rows (padded)
#define SM_A     34816                      // 128 x 144B bf16 rows (padded)
#define SM_B     53248                      // 1024 x 144B bf16 rows (padded)
#define SM_CN    200704                     // 1024 fp32
#define SM_RMAX  204800                     // 128 u32 keys (reused as reduce buf)
#define SM_CNT   205312                     // 128 int
#define SM_CAND  205824                     // 128 x 8 x 8B
#define SM_TOK   214016                     // 128 int
#define SM_DELTA 214528                     // 128 fp32
#define SM_FLAG  215040                     // 4B last-CTA flag
#define SMEM_TOTAL 215056

#define A_STRIDE 144
#define B_STRIDE 144
#define X_STRIDE 272

// ---------------- device globals ----------------
__device__ __align__(16) float    g_cnorm[KCODES];
__device__ __align__(16) uint32_t g_cbbf16[KCODES * DIMS / 2];
__device__ unsigned int           g_counts[KCODES];
__device__ float                  g_loss[2];
__device__ int                    g_cmax_bits;
__device__ unsigned int           g_done;

// ---------------- helpers ----------------
static __device__ __forceinline__ unsigned fkey(float f) {
    int b = __float_as_int(f);
    return (unsigned)(b >= 0 ? (b | 0x80000000) : ~b);
}
static __device__ __forceinline__ float finv(unsigned k) {
    int b = (k & 0x80000000u) ? (int)(k & 0x7fffffffu) : ~(int)k;
    return __int_as_float(b);
}
static __device__ __forceinline__ void mma16816(
    float& c0, float& c1, float& c2, float& c3,
    uint32_t a0, uint32_t a1, uint32_t a2, uint32_t a3,
    uint32_t b0, uint32_t b1)
{
    asm volatile(
        "mma.sync.aligned.m16n8k16.row.col.f32.bf16.bf16.f32 "
        "{%0,%1,%2,%3}, {%4,%5,%6,%7}, {%8,%9}, {%0,%1,%2,%3};"
        : "+f"(c0), "+f"(c1), "+f"(c2), "+f"(c3)
        : "r"(a0), "r"(a1), "r"(a2), "r"(a3), "r"(b0), "r"(b1));
}

// ---------------- prep: resets + cnorm + cmax + bf16 codebook ----------------
__global__ void vq_prep(const float* __restrict__ cb) {
    int k = threadIdx.x;   // 1024 threads, 1 block
    g_counts[k] = 0u;
    if (k < 2) g_loss[k] = 0.0f;
    if (k == 2) g_done = 0u;

    const float4* c4 = (const float4*)(cb + (size_t)k * DIMS);
    uint32_t* ob = g_cbbf16 + k * (DIMS / 2);
    float s = 0.0f;
#pragma unroll
    for (int j = 0; j < 16; j++) {
        float4 v = c4[j];
        s += v.x * v.x + v.y * v.y + v.z * v.z + v.w * v.w;
        __nv_bfloat162 p0 = __float22bfloat162_rn(make_float2(v.x, v.y));
        __nv_bfloat162 p1 = __float22bfloat162_rn(make_float2(v.z, v.w));
        ob[j * 2 + 0] = *(uint32_t*)&p0;
        ob[j * 2 + 1] = *(uint32_t*)&p1;
    }
    g_cnorm[k] = 0.5f * s;
    atomicMax(&g_cmax_bits, __float_as_int(sqrtf(s)));   // idempotent across calls
}

// ---------------- main ----------------
extern __shared__ char smem[];

__global__ __launch_bounds__(THREADS, 1)
void vq_main(const float* __restrict__ inp, const float* __restrict__ cb,
             float* __restrict__ out)
{
    const int tid  = threadIdx.x;
    const int w    = tid >> 5;
    const int lane = tid & 31;
    const int row0 = blockIdx.x * BM;

    float*    Xs = (float*)(smem + SM_X);
    char*     As = smem + SM_A;
    char*     Bs = smem + SM_B;
    float*    CN = (float*)(smem + SM_CN);
    unsigned* RM = (unsigned*)(smem + SM_RMAX);
    int*      CT = (int*)(smem + SM_CNT);
    float2*   CA = (float2*)(smem + SM_CAND);
    int*      TK = (int*)(smem + SM_TOK);
    float*    DL = (float*)(smem + SM_DELTA);
    int*      FLAG = (int*)(smem + SM_FLAG);

    // ---- fills ----
    if (tid < 128) { RM[tid] = 0u; CT[tid] = 0; }
#pragma unroll
    for (int i = 0; i < 4; i++) {           // X fp32 + A bf16
        int idx = tid + i * THREADS;
        int r = idx >> 4, j = idx & 15;
        float4 v = *(const float4*)(inp + (size_t)(row0 + r) * DIMS + j * 4);
        *(float4*)(Xs + r * (X_STRIDE / 4) + j * 4) = v;
        __nv_bfloat162 p0 = __float22bfloat162_rn(make_float2(v.x, v.y));
        __nv_bfloat162 p1 = __float22bfloat162_rn(make_float2(v.z, v.w));
        *(uint2*)(As + r * A_STRIDE + j * 8) = make_uint2(*(uint32_t*)&p0, *(uint32_t*)&p1);
    }
#pragma unroll
    for (int i = 0; i < 16; i++) {          // B bf16
        int idx = tid + i * THREADS;
        int c = idx >> 3, j = idx & 7;
        uint4 v = *(const uint4*)(g_cbbf16 + (size_t)idx * 4);
        *(uint4*)(Bs + c * B_STRIDE + j * 16) = v;
    }
#pragma unroll
    for (int i = 0; i < 2; i++) {           // cnorm
        int idx = tid + i * THREADS;
        CN[idx] = g_cnorm[idx];
    }
    __syncthreads();

    // ---- per-row certified margin delta ----
    if (tid < 128) {
        const float4* xr = (const float4*)(Xs + tid * (X_STRIDE / 4));
        float s = 0.0f;
#pragma unroll
        for (int j = 0; j < 16; j++) {
            float4 v = xr[j];
            s += v.x * v.x + v.y * v.y + v.z * v.z + v.w * v.w;
        }
        DL[tid] = sqrtf(s) * __int_as_float(g_cmax_bits) * (2.2f / 256.0f) + 1e-4f;
    }
    __syncthreads();

    // ---- warp work assignment: 32 rows x 256 codes ----
    const int rowblk = (w & 3) * 32;
    const int colq   = (w >> 2) * 256;
    const int ra = rowblk + (lane >> 2);
    const int rb = ra + 8;
    const int rc = ra + 16;
    const int rd = ra + 24;

    // ---- A fragments: persistent registers (4 ks x {blk0:4, blk1:4}) ----
    uint32_t af[4][8];
#pragma unroll
    for (int ks = 0; ks < 4; ks++) {
        int kb = ks * 32 + (lane & 3) * 4;
        af[ks][0] = *(const uint32_t*)(As + ra * A_STRIDE + kb);
        af[ks][1] = *(const uint32_t*)(As + rb * A_STRIDE + kb);
        af[ks][2] = *(const uint32_t*)(As + ra * A_STRIDE + kb + 16);
        af[ks][3] = *(const uint32_t*)(As + rb * A_STRIDE + kb + 16);
        af[ks][4] = *(const uint32_t*)(As + rc * A_STRIDE + kb);
        af[ks][5] = *(const uint32_t*)(As + rd * A_STRIDE + kb);
        af[ks][6] = *(const uint32_t*)(As + rc * A_STRIDE + kb + 16);
        af[ks][7] = *(const uint32_t*)(As + rd * A_STRIDE + kb + 16);
    }

    // ================= PASS 1: exact approx-max per row =================
    float gma[8], gmb[8], gmc[8], gmd[8];
#pragma unroll
    for (int g = 0; g < 8; g++) {
        gma[g] = -3.4e38f; gmb[g] = -3.4e38f;
        gmc[g] = -3.4e38f; gmd[g] = -3.4e38f;
    }

#pragma unroll 4
    for (int j = 0; j < 32; ++j) {
        int col0 = colq + j * 8 + (lane & 3) * 2;
        float2 cn = *(const float2*)(CN + col0);
        float ac0[4] = { -cn.x, -cn.y, -cn.x, -cn.y };
        float ac1[4] = { -cn.x, -cn.y, -cn.x, -cn.y };
        const char* bbase = Bs + (colq + j * 8 + (lane >> 2)) * B_STRIDE + (lane & 3) * 4;
#pragma unroll
        for (int ks = 0; ks < 4; ks++) {
            uint32_t b0 = *(const uint32_t*)(bbase + ks * 32);
            uint32_t b1 = *(const uint32_t*)(bbase + ks * 32 + 16);
            mma16816(ac0[0], ac0[1], ac0[2], ac0[3],
                     af[ks][0], af[ks][1], af[ks][2], af[ks][3], b0, b1);
            mma16816(ac1[0], ac1[1], ac1[2], ac1[3],
                     af[ks][4], af[ks][5], af[ks][6], af[ks][7], b0, b1);
        }
        int g = j >> 2;
        gma[g] = fmaxf(gma[g], fmaxf(ac0[0], ac0[1]));
        gmb[g] = fmaxf(gmb[g], fmaxf(ac0[2], ac0[3]));
        gmc[g] = fmaxf(gmc[g], fmaxf(ac1[0], ac1[1]));
        gmd[g] = fmaxf(gmd[g], fmaxf(ac1[2], ac1[3]));
    }

    // quad-combine (lanes of a quad share the same rows)
    float rma = -3.4e38f, rmb = -3.4e38f, rmc = -3.4e38f, rmd = -3.4e38f;
#pragma unroll
    for (int g = 0; g < 8; g++) {
        gma[g] = fmaxf(gma[g], __shfl_xor_sync(0xffffffffu, gma[g], 1));
        gma[g] = fmaxf(gma[g], __shfl_xor_sync(0xffffffffu, gma[g], 2));
        gmb[g] = fmaxf(gmb[g], __shfl_xor_sync(0xffffffffu, gmb[g], 1));
        gmb[g] = fmaxf(gmb[g], __shfl_xor_sync(0xffffffffu, gmb[g], 2));
        gmc[g] = fmaxf(gmc[g], __shfl_xor_sync(0xffffffffu, gmc[g], 1));
        gmc[g] = fmaxf(gmc[g], __shfl_xor_sync(0xffffffffu, gmc[g], 2));
        gmd[g] = fmaxf(gmd[g], __shfl_xor_sync(0xffffffffu, gmd[g], 1));
        gmd[g] = fmaxf(gmd[g], __shfl_xor_sync(0xffffffffu, gmd[g], 2));
        rma = fmaxf(rma, gma[g]); rmb = fmaxf(rmb, gmb[g]);
        rmc = fmaxf(rmc, gmc[g]); rmd = fmaxf(rmd, gmd[g]);
    }
    if ((lane & 3) == 0) {
        atomicMax(&RM[ra], fkey(rma));
        atomicMax(&RM[rb], fkey(rmb));
        atomicMax(&RM[rc], fkey(rmc));
        atomicMax(&RM[rd], fkey(rmd));
    }
    __syncthreads();

    // ================= PASS 2: fixed-threshold candidate collection =================
    const float thra = finv(RM[ra]) - DL[ra];
    const float thrb = finv(RM[rb]) - DL[rb];
    const float thrc = finv(RM[rc]) - DL[rc];
    const float thrd = finv(RM[rd]) - DL[rd];

#define PUSH(val, row, col) do {                                            \
        if ((val) >= thr_##row) {                                           \
            int p = atomicAdd(&CT[row], 1);                                 \
            if (p < CAND_CAP)                                               \
                CA[(row) * CAND_CAP + p] =                                  \
                    make_float2((val), __int_as_float(col));                \
        }                                                                   \
    } while (0)

    for (int g = 0; g < 8; g++) {
        bool need = (gma[g] >= thra) || (gmb[g] >= thrb) ||
                    (gmc[g] >= thrc) || (gmd[g] >= thrd);
        if (!__any_sync(0xffffffffu, need)) continue;
#pragma unroll
        for (int jj = 0; jj < 4; jj++) {
            int j = g * 4 + jj;
            int col0 = colq + j * 8 + (lane & 3) * 2;
            float2 cn = *(const float2*)(CN + col0);
            float ac0[4] = { -cn.x, -cn.y, -cn.x, -cn.y };
            float ac1[4] = { -cn.x, -cn.y, -cn.x, -cn.y };
            const char* bbase = Bs + (colq + j * 8 + (lane >> 2)) * B_STRIDE + (lane & 3) * 4;
#pragma unroll
            for (int ks = 0; ks < 4; ks++) {
                uint32_t b0 = *(const uint32_t*)(bbase + ks * 32);
                uint32_t b1 = *(const uint32_t*)(bbase + ks * 32 + 16);
                mma16816(ac0[0], ac0[1], ac0[2], ac0[3],
                         af[ks][0], af[ks][1], af[ks][2], af[ks][3], b0, b1);
                mma16816(ac1[0], ac1[1], ac1[2], ac1[3],
                         af[ks][4], af[ks][5], af[ks][6], af[ks][7], b0, b1);
            }
            {
                const float thr_ra = thra, thr_rb = thrb, thr_rc = thrc, thr_rd = thrd;
                PUSH(ac0[0], ra, col0); PUSH(ac0[1], ra, col0 + 1);
                PUSH(ac0[2], rb, col0); PUSH(ac0[3], rb, col0 + 1);
                PUSH(ac1[0], rc, col0); PUSH(ac1[1], rc, col0 + 1);
                PUSH(ac1[2], rd, col0); PUSH(ac1[3], rd, col0 + 1);
            }
        }
    }
#undef PUSH
    __syncthreads();

    // ---- exact fp32 rescore (1 thread per row) ----
    if (tid < 128) {
        int r = tid;
        int n = CT[r];
        const float* xrow = Xs + r * (X_STRIDE / 4);
        float bestS = -3.4e38f;
        int   bestI = KCODES;
        if (n <= CAND_CAP) {
            for (int i = 0; i < n; i++) {
                float2 ce = CA[r * CAND_CAP + i];
                int ix = __float_as_int(ce.y);
                const float4* c4 = (const float4*)(cb + (size_t)ix * DIMS);
                float a0 = 0.f, a1 = 0.f, a2 = 0.f, a3 = 0.f;
#pragma unroll
                for (int q = 0; q < 16; q++) {
                    float4 cv = c4[q];
                    float4 xv = *(const float4*)(xrow + q * 4);
                    a0 = fmaf(xv.x, cv.x, a0);
                    a1 = fmaf(xv.y, cv.y, a1);
                    a2 = fmaf(xv.z, cv.z, a2);
                    a3 = fmaf(xv.w, cv.w, a3);
                }
                float s = (a0 + a1) + (a2 + a3) - CN[ix];
                if (s > bestS || (s == bestS && ix < bestI)) { bestS = s; bestI = ix; }
            }
        } else {
            // overflow fallback (astronomically rare): exact full scan
            for (int ix = 0; ix < KCODES; ix++) {
                const float4* c4 = (const float4*)(cb + (size_t)ix * DIMS);
                float a0 = 0.f, a1 = 0.f, a2 = 0.f, a3 = 0.f;
#pragma unroll
                for (int q = 0; q < 16; q++) {
                    float4 cv = c4[q];
                    float4 xv = *(const float4*)(xrow + q * 4);
                    a0 = fmaf(xv.x, cv.x, a0);
                    a1 = fmaf(xv.y, cv.y, a1);
                    a2 = fmaf(xv.z, cv.z, a2);
                    a3 = fmaf(xv.w, cv.w, a3);
                }
                float s = (a0 + a1) + (a2 + a3) - CN[ix];
                if (s > bestS) { bestS = s; bestI = ix; }
            }
        }
        TK[r] = bestI;
        out[QOUT + row0 + r] = (float)bestI;
        atomicAdd(&g_counts[bestI], 1u);
    }
    __syncthreads();

    // ---- quantized + straight-through + losses (cooperative, coalesced) ----
    float esum = 0.0f, qsum = 0.0f;
#pragma unroll
    for (int i = 0; i < 4; i++) {
        int idx = tid + i * THREADS;
        int r = idx >> 4, q = idx & 15;
        int ix = TK[r];
        float4 cv = *(const float4*)(cb + (size_t)ix * DIMS + q * 4);
        float4 xv = *(const float4*)(Xs + r * (X_STRIDE / 4) + q * 4);
        float d0v = cv.x - xv.x, d1v = cv.y - xv.y, d2v = cv.z - xv.z, d3v = cv.w - xv.w;
        float q0 = xv.x + d0v, q1 = xv.y + d1v, q2 = xv.z + d2v, q3 = xv.w + d3v;
        float e0 = q0 - xv.x, e1 = q1 - xv.y, e2 = q2 - xv.z, e3 = q3 - xv.w;
        esum += e0 * e0 + e1 * e1 + e2 * e2 + e3 * e3;
        qsum += d0v * d0v + d1v * d1v + d2v * d2v + d3v * d3v;
        *(float4*)(out + (size_t)(row0 + r) * DIMS + q * 4) = make_float4(q0, q1, q2, q3);
    }
#pragma unroll
    for (int off = 16; off > 0; off >>= 1) {
        esum += __shfl_xor_sync(0xffffffffu, esum, off);
        qsum += __shfl_xor_sync(0xffffffffu, qsum, off);
    }
    if (lane == 0) {
        atomicAdd(&g_loss[0], esum);
        atomicAdd(&g_loss[1], qsum);
    }

    // ---- last-CTA finalize (perplexity + scalar losses) ----
    if (tid == 0) {
        __threadfence();
        *FLAG = (atomicAdd(&g_done, 1u) == GRID - 1) ? 1 : 0;
    }
    __syncthreads();
    if (*FLAG) {
        volatile unsigned* vc = g_counts;
        float part = 0.0f;
#pragma unroll
        for (int i = 0; i < 2; i++) {
            float p = (float)vc[tid + i * THREADS] / (float)N_ROWS;
            part += -p * logf(p + 1e-10f);
        }
#pragma unroll
        for (int off = 16; off > 0; off >>= 1)
            part += __shfl_xor_sync(0xffffffffu, part, off);
        float* red = (float*)RM;            // reuse: 16 warp partials
        if (lane == 0) red[w] = part;
        __syncthreads();
        if (tid == 0) {
            float H = 0.0f;
#pragma unroll
            for (int i = 0; i < 16; i++) H += red[i];
            volatile float* vl = g_loss;
            float inv = 1.0f / (float)((long long)N_ROWS * DIMS);
            float e_mean = vl[0] * inv;
            float q_mean = vl[1] * inv;
            float commit = 0.25f * e_mean;
            out[QOUT + N_ROWS + 0] = commit + q_mean;
            out[QOUT + N_ROWS + 1] = commit;
            out[QOUT + N_ROWS + 2] = q_mean;
            out[QOUT + N_ROWS + 3] = expf(H);
        }
    }
}

extern "C" void kernel_launch(void* const* d_in, const int* in_sizes, int n_in,
                              void* d_out, int out_size)
{
    const float* inp = (const float*)d_in[0];
    const float* cb  = (const float*)d_in[1];
    float* out = (float*)d_out;

    cudaFuncSetAttribute(vq_main, cudaFuncAttributeMaxDynamicSharedMemorySize, SMEM_TOTAL);

    vq_prep<<<1, 1024>>>(cb);
    vq_main<<<GRID, THREADS, SMEM_TOTAL>>>(inp, cb, out);
}